// round 11
// baseline (speedup 1.0000x reference)
#include <cuda_runtime.h>
#include <cuda_fp16.h>

// GaussianWarpingScheme on GB300 — round 11.
// FUSED, batch-interleaved: grid = 8 batches x 512 blocks.
//   per batch: blocks [0,256)  = producers (transpose one (b,h) row to fp16 HWC scratch)
//              blocks [256,512) = consumers (round-9 gather: 2 px/lane, 8 ch/lane)
// Consumers gate on a per-batch counter; 256th consumer block resets the
// counters so every launch (graph replay) starts from zero state.

#define Bn 8
#define Cn 16
#define Hn 256
#define Wn 256
#define HWn (Hn * Wn)

__device__ __half g_imH[(size_t)Bn * HWn * Cn];   // 32 MB channel-last scratch
__device__ int    g_cnt[Bn];                      // producer completions per batch
__device__ int    g_done[Bn];                     // consumer completions per batch

// ---- packed f32x2 helpers ----
__device__ __forceinline__ unsigned long long f2pack(float lo, float hi) {
    unsigned long long r;
    asm("mov.b64 %0,{%1,%2};" : "=l"(r) : "f"(lo), "f"(hi));
    return r;
}
__device__ __forceinline__ unsigned long long h2f2(unsigned int h2) {
    const float2 f = __half22float2(*(const __half2*)&h2);
    return f2pack(f.x, f.y);
}
__device__ __forceinline__ unsigned long long fma2(unsigned long long a,
                                                   unsigned long long b,
                                                   unsigned long long c) {
    unsigned long long d;
    asm("fma.rn.f32x2 %0,%1,%2,%3;" : "=l"(d) : "l"(a), "l"(b), "l"(c));
    return d;
}
__device__ __forceinline__ unsigned long long mul2(unsigned long long a,
                                                   unsigned long long b) {
    unsigned long long d;
    asm("mul.rn.f32x2 %0,%1,%2;" : "=l"(d) : "l"(a), "l"(b));
    return d;
}
__device__ __forceinline__ float2 f2unpack(unsigned long long a) {
    float2 f;
    asm("mov.b64 {%0,%1},%2;" : "=f"(f.x), "=f"(f.y) : "l"(a));
    return f;
}

// ---------------- per-pixel params ----------------
struct PixParams {
    unsigned long long W00, W01, W10, W11;
    const __half* p0;
    const __half* p1;
    float* op;
};

__device__ __forceinline__ PixParams
pix_params(int p, int csel, const float* __restrict__ w, float* __restrict__ out)
{
    const int b   = p >> 16;
    const int rem = p & (HWn - 1);
    const int ho  = rem >> 8;
    const int wo  = rem & (Wn - 1);

    const float w0 = w[b * 2 * HWn + rem];
    const float w1 = w[b * 2 * HWn + HWn + rem];

    const float bx = -1.0f + (float)wo * (2.0f / 255.0f);
    const float by = -1.0f + (float)ho * (2.0f / 255.0f);
    const float x = ((bx - w0) + 1.0f) * 0.5f * 255.0f;
    const float y = ((by - w1) + 1.0f) * 0.5f * 255.0f;
    const int ix = (int)floorf(x);
    const int iy = (int)floorf(y);
    const float fx = x - (float)ix;
    const float fy = y - (float)iy;

    const float wx0m = (ix     >= 0 && ix     < Wn) ? __expf(-8.0f * fx * fx)               : 0.0f;
    const float wx1m = (ix + 1 >= 0 && ix + 1 < Wn) ? __expf(-8.0f * (1.0f-fx) * (1.0f-fx)) : 0.0f;
    const float wy0m = (iy     >= 0 && iy     < Hn) ? __expf(-8.0f * fy * fy)               : 0.0f;
    const float wy1m = (iy + 1 >= 0 && iy + 1 < Hn) ? __expf(-8.0f * (1.0f-fy) * (1.0f-fy)) : 0.0f;

    const int xb = min(max(ix, 0), Wn - 2);
    float pw0 = 0.0f, pw1 = 0.0f;
    if (ix     == xb)     pw0 += wx0m;
    if (ix + 1 == xb)     pw0 += wx1m;            // ix = -1
    if (ix     == xb + 1) pw1 += wx0m;            // ix = 255
    if (ix + 1 == xb + 1) pw1 += wx1m;

    const int y0 = min(max(iy,     0), Hn - 1);
    const int y1 = min(max(iy + 1, 0), Hn - 1);

    PixParams r;
    r.W00 = f2pack(pw0 * wy0m, pw0 * wy0m);
    r.W01 = f2pack(pw1 * wy0m, pw1 * wy0m);
    r.W10 = f2pack(pw0 * wy1m, pw0 * wy1m);
    r.W11 = f2pack(pw1 * wy1m, pw1 * wy1m);

    const __half* bh = g_imH + (size_t)b * HWn * Cn;
    r.p0 = bh + (size_t)((y0 << 8) + xb) * Cn + csel * 8;
    r.p1 = bh + (size_t)((y1 << 8) + xb) * Cn + csel * 8;
    r.op = out + (size_t)b * Cn * HWn + (size_t)(csel * 8) * HWn + rem;
    return r;
}

// ---------------- fused kernel, batch-interleaved ----------------
__global__ void __launch_bounds__(256)
gauss_warp_fused(const float* __restrict__ im,
                 const float* __restrict__ w,
                 float* __restrict__ out)
{
    const int bid    = blockIdx.x;
    const int tid    = threadIdx.x;
    const int batch  = bid >> 9;          // / 512
    const int within = bid & 511;

    if (within < Hn) {
        // ================= producer: transpose row (batch, within) =================
        const int h  = within;
        const int wv = tid;

        const float* src = im + ((size_t)(batch * Cn) * Hn + h) * Wn + wv;
        __half* dst = g_imH + ((size_t)((batch << 8) + h) * Wn + wv) * Cn;

        __half hv[Cn];
#pragma unroll
        for (int c = 0; c < Cn; c++)
            hv[c] = __float2half_rn(src[(size_t)c * HWn]);

        *(uint4*)(dst)     = *(const uint4*)(hv);
        *(uint4*)(dst + 8) = *(const uint4*)(hv + 8);

        __threadfence();
        __syncthreads();
        if (tid == 0) atomicAdd(&g_cnt[batch], 1);
        return;
    }

    // ================= consumer: 256 pixels (2 px/lane) =================
    const int cblk = within - Hn;         // 0..255
    const int q    = tid >> 1;
    const int csel = tid & 1;

    const int pA = batch * HWn + cblk * 256 + q;
    const int pB = pA + 128;

    // acquire: wait for all 256 producer rows of this batch
    if (tid == 0) {
        while (*(volatile int*)&g_cnt[batch] < Hn) __nanosleep(32);
    }
    __syncthreads();
    __threadfence();

    const PixParams a  = pix_params(pA, csel, w, out);
    const PixParams bp = pix_params(pB, csel, w, out);

    const uint4 a00 = __ldg((const uint4*)a.p0);
    const uint4 a01 = __ldg((const uint4*)a.p0 + 2);
    const uint4 a10 = __ldg((const uint4*)a.p1);
    const uint4 a11 = __ldg((const uint4*)a.p1 + 2);
    const uint4 b00 = __ldg((const uint4*)bp.p0);
    const uint4 b01 = __ldg((const uint4*)bp.p0 + 2);
    const uint4 b10 = __ldg((const uint4*)bp.p1);
    const uint4 b11 = __ldg((const uint4*)bp.p1 + 2);

    unsigned long long s0, s1, s2, s3;
    s0 = mul2(a.W00, h2f2(a00.x));
    s1 = mul2(a.W00, h2f2(a00.y));
    s2 = mul2(a.W00, h2f2(a00.z));
    s3 = mul2(a.W00, h2f2(a00.w));
    s0 = fma2(a.W01, h2f2(a01.x), s0);
    s1 = fma2(a.W01, h2f2(a01.y), s1);
    s2 = fma2(a.W01, h2f2(a01.z), s2);
    s3 = fma2(a.W01, h2f2(a01.w), s3);
    s0 = fma2(a.W10, h2f2(a10.x), s0);
    s1 = fma2(a.W10, h2f2(a10.y), s1);
    s2 = fma2(a.W10, h2f2(a10.z), s2);
    s3 = fma2(a.W10, h2f2(a10.w), s3);
    s0 = fma2(a.W11, h2f2(a11.x), s0);
    s1 = fma2(a.W11, h2f2(a11.y), s1);
    s2 = fma2(a.W11, h2f2(a11.z), s2);
    s3 = fma2(a.W11, h2f2(a11.w), s3);
    {
        const float2 f0 = f2unpack(s0);
        const float2 f1 = f2unpack(s1);
        const float2 f2 = f2unpack(s2);
        const float2 f3 = f2unpack(s3);
        a.op[0 * HWn] = f0.x;  a.op[1 * HWn] = f0.y;
        a.op[2 * HWn] = f1.x;  a.op[3 * HWn] = f1.y;
        a.op[4 * HWn] = f2.x;  a.op[5 * HWn] = f2.y;
        a.op[6 * HWn] = f3.x;  a.op[7 * HWn] = f3.y;
    }

    s0 = mul2(bp.W00, h2f2(b00.x));
    s1 = mul2(bp.W00, h2f2(b00.y));
    s2 = mul2(bp.W00, h2f2(b00.z));
    s3 = mul2(bp.W00, h2f2(b00.w));
    s0 = fma2(bp.W01, h2f2(b01.x), s0);
    s1 = fma2(bp.W01, h2f2(b01.y), s1);
    s2 = fma2(bp.W01, h2f2(b01.z), s2);
    s3 = fma2(bp.W01, h2f2(b01.w), s3);
    s0 = fma2(bp.W10, h2f2(b10.x), s0);
    s1 = fma2(bp.W10, h2f2(b10.y), s1);
    s2 = fma2(bp.W10, h2f2(b10.z), s2);
    s3 = fma2(bp.W10, h2f2(b10.w), s3);
    s0 = fma2(bp.W11, h2f2(b11.x), s0);
    s1 = fma2(bp.W11, h2f2(b11.y), s1);
    s2 = fma2(bp.W11, h2f2(b11.z), s2);
    s3 = fma2(bp.W11, h2f2(b11.w), s3);
    {
        const float2 f0 = f2unpack(s0);
        const float2 f1 = f2unpack(s1);
        const float2 f2 = f2unpack(s2);
        const float2 f3 = f2unpack(s3);
        bp.op[0 * HWn] = f0.x;  bp.op[1 * HWn] = f0.y;
        bp.op[2 * HWn] = f1.x;  bp.op[3 * HWn] = f1.y;
        bp.op[4 * HWn] = f2.x;  bp.op[5 * HWn] = f2.y;
        bp.op[6 * HWn] = f3.x;  bp.op[7 * HWn] = f3.y;
    }

    // self-reset: last consumer block of this batch zeroes the counters
    __syncthreads();
    if (tid == 0) {
        const int done = atomicAdd(&g_done[batch], 1);
        if (done == Hn - 1) {            // 256 consumer blocks per batch
            g_cnt[batch]  = 0;
            g_done[batch] = 0;
        }
    }
}

extern "C" void kernel_launch(void* const* d_in, const int* in_sizes, int n_in,
                              void* d_out, int out_size)
{
    const float* im = (const float*)d_in[0];
    const float* w  = (const float*)d_in[1];
    if (n_in >= 2 && in_sizes[0] == Bn * 2 * HWn && in_sizes[1] == Bn * Cn * HWn) {
        im = (const float*)d_in[1];
        w  = (const float*)d_in[0];
    }
    float* out = (float*)d_out;

    gauss_warp_fused<<<Bn * 512, 256>>>(im, w, out);
}

// round 12
// speedup vs baseline: 1.3797x; 1.3797x over previous
#include <cuda_runtime.h>
#include <cuda_fp16.h>

// GaussianWarpingScheme on GB300 — round 12 (revert r9 + paired stores).
// Pass 1: transpose im (B,C,H,W) f32 -> scratch (B,H,W,C) fp16 (LTS-capped).
// Pass 2: warp-independent, 2 ADJACENT pixels per lane (2q, 2q+1), 8 ch/lane.
//   8 gather LDG.128 issued up front (MLP=8/lane), FFMA2 accumulate,
//   8x STG.64 (pixel-pair per channel) -> store wavefronts halved.

#define Bn 8
#define Cn 16
#define Hn 256
#define Wn 256
#define HWn (Hn * Wn)

__device__ __half g_imH[(size_t)Bn * HWn * Cn];   // 32 MB channel-last scratch

// ---- packed f32x2 helpers ----
__device__ __forceinline__ unsigned long long f2pack(float lo, float hi) {
    unsigned long long r;
    asm("mov.b64 %0,{%1,%2};" : "=l"(r) : "f"(lo), "f"(hi));
    return r;
}
__device__ __forceinline__ unsigned long long h2f2(unsigned int h2) {
    const float2 f = __half22float2(*(const __half2*)&h2);
    return f2pack(f.x, f.y);
}
__device__ __forceinline__ unsigned long long fma2(unsigned long long a,
                                                   unsigned long long b,
                                                   unsigned long long c) {
    unsigned long long d;
    asm("fma.rn.f32x2 %0,%1,%2,%3;" : "=l"(d) : "l"(a), "l"(b), "l"(c));
    return d;
}
__device__ __forceinline__ unsigned long long mul2(unsigned long long a,
                                                   unsigned long long b) {
    unsigned long long d;
    asm("mul.rn.f32x2 %0,%1,%2;" : "=l"(d) : "l"(a), "l"(b));
    return d;
}
__device__ __forceinline__ float2 f2unpack(unsigned long long a) {
    float2 f;
    asm("mov.b64 {%0,%1},%2;" : "=f"(f.x), "=f"(f.y) : "l"(a));
    return f;
}

// ---------------- Pass 1: (B,C,H,W) f32 -> (B,H,W,C) fp16 ----------------
__global__ void __launch_bounds__(256)
transpose_chw_hwc(const float* __restrict__ im)
{
    const int bh = blockIdx.x;          // 0 .. B*H-1
    const int b  = bh >> 8;
    const int h  = bh & (Hn - 1);
    const int wv = threadIdx.x;

    const float* src = im + ((size_t)(b * Cn) * Hn + h) * Wn + wv;
    __half* dst = g_imH + ((size_t)((b << 8) + h) * Wn + wv) * Cn;

    __half hv[Cn];
#pragma unroll
    for (int c = 0; c < Cn; c++)
        hv[c] = __float2half_rn(src[(size_t)c * HWn]);

    *(uint4*)(dst)     = *(const uint4*)(hv);
    *(uint4*)(dst + 8) = *(const uint4*)(hv + 8);
}

// ---------------- per-pixel params ----------------
struct PixParams {
    unsigned long long W00, W01, W10, W11;
    const __half* p0;
    const __half* p1;
};

__device__ __forceinline__ PixParams
pix_params(int b, int rem, int csel, const float* __restrict__ w)
{
    const int ho = rem >> 8;
    const int wo = rem & (Wn - 1);

    const float w0 = w[b * 2 * HWn + rem];
    const float w1 = w[b * 2 * HWn + HWn + rem];

    const float bx = -1.0f + (float)wo * (2.0f / 255.0f);
    const float by = -1.0f + (float)ho * (2.0f / 255.0f);
    const float x = ((bx - w0) + 1.0f) * 0.5f * 255.0f;
    const float y = ((by - w1) + 1.0f) * 0.5f * 255.0f;
    const int ix = (int)floorf(x);
    const int iy = (int)floorf(y);
    const float fx = x - (float)ix;
    const float fy = y - (float)iy;

    const float wx0m = (ix     >= 0 && ix     < Wn) ? __expf(-8.0f * fx * fx)               : 0.0f;
    const float wx1m = (ix + 1 >= 0 && ix + 1 < Wn) ? __expf(-8.0f * (1.0f-fx) * (1.0f-fx)) : 0.0f;
    const float wy0m = (iy     >= 0 && iy     < Hn) ? __expf(-8.0f * fy * fy)               : 0.0f;
    const float wy1m = (iy + 1 >= 0 && iy + 1 < Hn) ? __expf(-8.0f * (1.0f-fy) * (1.0f-fy)) : 0.0f;

    // x-pair base with boundary-correct slot weights
    const int xb = min(max(ix, 0), Wn - 2);
    float pw0 = 0.0f, pw1 = 0.0f;
    if (ix     == xb)     pw0 += wx0m;
    if (ix + 1 == xb)     pw0 += wx1m;            // ix = -1
    if (ix     == xb + 1) pw1 += wx0m;            // ix = 255
    if (ix + 1 == xb + 1) pw1 += wx1m;

    const int y0 = min(max(iy,     0), Hn - 1);
    const int y1 = min(max(iy + 1, 0), Hn - 1);

    PixParams r;
    r.W00 = f2pack(pw0 * wy0m, pw0 * wy0m);
    r.W01 = f2pack(pw1 * wy0m, pw1 * wy0m);
    r.W10 = f2pack(pw0 * wy1m, pw0 * wy1m);
    r.W11 = f2pack(pw1 * wy1m, pw1 * wy1m);

    const __half* bh = g_imH + (size_t)b * HWn * Cn;
    r.p0 = bh + (size_t)((y0 << 8) + xb) * Cn + csel * 8;
    r.p1 = bh + (size_t)((y1 << 8) + xb) * Cn + csel * 8;
    return r;
}

// ---------------- Pass 2: 2 adjacent px/lane, paired stores ----------------
__global__ void __launch_bounds__(256)
gauss_warp_main(const float* __restrict__ w,
                float* __restrict__ out)
{
    const int tid  = threadIdx.x;
    const int q    = tid >> 1;                    // pixel-pair slot 0..127
    const int csel = tid & 1;                     // channel half

    const int pA  = blockIdx.x * 256 + 2 * q;     // adjacent pixels pA, pA+1
    const int b   = pA >> 16;
    const int rA  = pA & (HWn - 1);
    const int rB  = rA + 1;                       // same row (block spans one row)

    const PixParams a  = pix_params(b, rA, csel, w);
    const PixParams bp = pix_params(b, rB, csel, w);

    // ---- issue all 8 gathers up front (MLP = 8 per lane) ----
    const uint4 a00 = __ldg((const uint4*)a.p0);
    const uint4 a01 = __ldg((const uint4*)a.p0 + 2);
    const uint4 a10 = __ldg((const uint4*)a.p1);
    const uint4 a11 = __ldg((const uint4*)a.p1 + 2);
    const uint4 b00 = __ldg((const uint4*)bp.p0);
    const uint4 b01 = __ldg((const uint4*)bp.p0 + 2);
    const uint4 b10 = __ldg((const uint4*)bp.p1);
    const uint4 b11 = __ldg((const uint4*)bp.p1 + 2);

    // ---- pixel A accumulate ----
    unsigned long long s0, s1, s2, s3;
    s0 = mul2(a.W00, h2f2(a00.x));
    s1 = mul2(a.W00, h2f2(a00.y));
    s2 = mul2(a.W00, h2f2(a00.z));
    s3 = mul2(a.W00, h2f2(a00.w));
    s0 = fma2(a.W01, h2f2(a01.x), s0);
    s1 = fma2(a.W01, h2f2(a01.y), s1);
    s2 = fma2(a.W01, h2f2(a01.z), s2);
    s3 = fma2(a.W01, h2f2(a01.w), s3);
    s0 = fma2(a.W10, h2f2(a10.x), s0);
    s1 = fma2(a.W10, h2f2(a10.y), s1);
    s2 = fma2(a.W10, h2f2(a10.z), s2);
    s3 = fma2(a.W10, h2f2(a10.w), s3);
    s0 = fma2(a.W11, h2f2(a11.x), s0);
    s1 = fma2(a.W11, h2f2(a11.y), s1);
    s2 = fma2(a.W11, h2f2(a11.z), s2);
    s3 = fma2(a.W11, h2f2(a11.w), s3);

    // ---- pixel B accumulate ----
    unsigned long long t0, t1, t2, t3;
    t0 = mul2(bp.W00, h2f2(b00.x));
    t1 = mul2(bp.W00, h2f2(b00.y));
    t2 = mul2(bp.W00, h2f2(b00.z));
    t3 = mul2(bp.W00, h2f2(b00.w));
    t0 = fma2(bp.W01, h2f2(b01.x), t0);
    t1 = fma2(bp.W01, h2f2(b01.y), t1);
    t2 = fma2(bp.W01, h2f2(b01.z), t2);
    t3 = fma2(bp.W01, h2f2(b01.w), t3);
    t0 = fma2(bp.W10, h2f2(b10.x), t0);
    t1 = fma2(bp.W10, h2f2(b10.y), t1);
    t2 = fma2(bp.W10, h2f2(b10.z), t2);
    t3 = fma2(bp.W10, h2f2(b10.w), t3);
    t0 = fma2(bp.W11, h2f2(b11.x), t0);
    t1 = fma2(bp.W11, h2f2(b11.y), t1);
    t2 = fma2(bp.W11, h2f2(b11.z), t2);
    t3 = fma2(bp.W11, h2f2(b11.w), t3);

    const float2 fa0 = f2unpack(s0), fb0 = f2unpack(t0);
    const float2 fa1 = f2unpack(s1), fb1 = f2unpack(t1);
    const float2 fa2 = f2unpack(s2), fb2 = f2unpack(t2);
    const float2 fa3 = f2unpack(s3), fb3 = f2unpack(t3);

    // ---- paired stores: STG.64 per channel (pixels pA, pA+1 adjacent) ----
    float* op = out + (size_t)b * Cn * HWn + (size_t)(csel * 8) * HWn + rA;
    *(float2*)(op + 0 * HWn) = make_float2(fa0.x, fb0.x);
    *(float2*)(op + 1 * HWn) = make_float2(fa0.y, fb0.y);
    *(float2*)(op + 2 * HWn) = make_float2(fa1.x, fb1.x);
    *(float2*)(op + 3 * HWn) = make_float2(fa1.y, fb1.y);
    *(float2*)(op + 4 * HWn) = make_float2(fa2.x, fb2.x);
    *(float2*)(op + 5 * HWn) = make_float2(fa2.y, fb2.y);
    *(float2*)(op + 6 * HWn) = make_float2(fa3.x, fb3.x);
    *(float2*)(op + 7 * HWn) = make_float2(fa3.y, fb3.y);
}

extern "C" void kernel_launch(void* const* d_in, const int* in_sizes, int n_in,
                              void* d_out, int out_size)
{
    const float* im = (const float*)d_in[0];
    const float* w  = (const float*)d_in[1];
    if (n_in >= 2 && in_sizes[0] == Bn * 2 * HWn && in_sizes[1] == Bn * Cn * HWn) {
        im = (const float*)d_in[1];
        w  = (const float*)d_in[0];
    }
    float* out = (float*)d_out;

    transpose_chw_hwc<<<Bn * Hn, 256>>>(im);
    gauss_warp_main<<<(Bn * HWn) / 256, 256>>>(w, out);
}

// round 13
// speedup vs baseline: 1.5014x; 1.0882x over previous
#include <cuda_runtime.h>
#include <cuda_fp16.h>

// GaussianWarpingScheme on GB300 — round 13: round-9 body + PDL overlap.
// Pass 1: transpose im (B,C,H,W) f32 -> scratch (B,H,W,C) fp16; each block
//         triggers programmatic launch completion at entry.
// Pass 2 (PDL secondary): prologue (w loads + weights + addresses, scratch-
//         independent) runs overlapped with transpose; then
//         cudaGridDependencySynchronize(); then gathers + stores.

#define Bn 8
#define Cn 16
#define Hn 256
#define Wn 256
#define HWn (Hn * Wn)

__device__ __half g_imH[(size_t)Bn * HWn * Cn];   // 32 MB channel-last scratch

// ---- packed f32x2 helpers ----
__device__ __forceinline__ unsigned long long f2pack(float lo, float hi) {
    unsigned long long r;
    asm("mov.b64 %0,{%1,%2};" : "=l"(r) : "f"(lo), "f"(hi));
    return r;
}
__device__ __forceinline__ unsigned long long h2f2(unsigned int h2) {
    const float2 f = __half22float2(*(const __half2*)&h2);
    return f2pack(f.x, f.y);
}
__device__ __forceinline__ unsigned long long fma2(unsigned long long a,
                                                   unsigned long long b,
                                                   unsigned long long c) {
    unsigned long long d;
    asm("fma.rn.f32x2 %0,%1,%2,%3;" : "=l"(d) : "l"(a), "l"(b), "l"(c));
    return d;
}
__device__ __forceinline__ unsigned long long mul2(unsigned long long a,
                                                   unsigned long long b) {
    unsigned long long d;
    asm("mul.rn.f32x2 %0,%1,%2;" : "=l"(d) : "l"(a), "l"(b));
    return d;
}
__device__ __forceinline__ float2 f2unpack(unsigned long long a) {
    float2 f;
    asm("mov.b64 {%0,%1},%2;" : "=f"(f.x), "=f"(f.y) : "l"(a));
    return f;
}

// ---------------- Pass 1: (B,C,H,W) f32 -> (B,H,W,C) fp16 ----------------
__global__ void __launch_bounds__(256)
transpose_chw_hwc(const float* __restrict__ im)
{
#if __CUDA_ARCH__ >= 900
    if (threadIdx.x == 0) cudaTriggerProgrammaticLaunchCompletion();
#endif
    const int bh = blockIdx.x;          // 0 .. B*H-1
    const int b  = bh >> 8;
    const int h  = bh & (Hn - 1);
    const int wv = threadIdx.x;

    const float* src = im + ((size_t)(b * Cn) * Hn + h) * Wn + wv;
    __half* dst = g_imH + ((size_t)((b << 8) + h) * Wn + wv) * Cn;

    __half hv[Cn];
#pragma unroll
    for (int c = 0; c < Cn; c++)
        hv[c] = __float2half_rn(src[(size_t)c * HWn]);

    *(uint4*)(dst)     = *(const uint4*)(hv);
    *(uint4*)(dst + 8) = *(const uint4*)(hv + 8);
}

// ---------------- per-pixel params (scratch-independent prologue) ----------
struct PixParams {
    unsigned long long W00, W01, W10, W11;
    const __half* p0;
    const __half* p1;
    float* op;
};

__device__ __forceinline__ PixParams
pix_params(int p, int csel, const float* __restrict__ w, float* __restrict__ out)
{
    const int b   = p >> 16;
    const int rem = p & (HWn - 1);
    const int ho  = rem >> 8;
    const int wo  = rem & (Wn - 1);

    const float w0 = w[b * 2 * HWn + rem];
    const float w1 = w[b * 2 * HWn + HWn + rem];

    const float bx = -1.0f + (float)wo * (2.0f / 255.0f);
    const float by = -1.0f + (float)ho * (2.0f / 255.0f);
    const float x = ((bx - w0) + 1.0f) * 0.5f * 255.0f;
    const float y = ((by - w1) + 1.0f) * 0.5f * 255.0f;
    const int ix = (int)floorf(x);
    const int iy = (int)floorf(y);
    const float fx = x - (float)ix;
    const float fy = y - (float)iy;

    const float wx0m = (ix     >= 0 && ix     < Wn) ? __expf(-8.0f * fx * fx)               : 0.0f;
    const float wx1m = (ix + 1 >= 0 && ix + 1 < Wn) ? __expf(-8.0f * (1.0f-fx) * (1.0f-fx)) : 0.0f;
    const float wy0m = (iy     >= 0 && iy     < Hn) ? __expf(-8.0f * fy * fy)               : 0.0f;
    const float wy1m = (iy + 1 >= 0 && iy + 1 < Hn) ? __expf(-8.0f * (1.0f-fy) * (1.0f-fy)) : 0.0f;

    const int xb = min(max(ix, 0), Wn - 2);
    float pw0 = 0.0f, pw1 = 0.0f;
    if (ix     == xb)     pw0 += wx0m;
    if (ix + 1 == xb)     pw0 += wx1m;            // ix = -1
    if (ix     == xb + 1) pw1 += wx0m;            // ix = 255
    if (ix + 1 == xb + 1) pw1 += wx1m;

    const int y0 = min(max(iy,     0), Hn - 1);
    const int y1 = min(max(iy + 1, 0), Hn - 1);

    PixParams r;
    r.W00 = f2pack(pw0 * wy0m, pw0 * wy0m);
    r.W01 = f2pack(pw1 * wy0m, pw1 * wy0m);
    r.W10 = f2pack(pw0 * wy1m, pw0 * wy1m);
    r.W11 = f2pack(pw1 * wy1m, pw1 * wy1m);

    const __half* bh = g_imH + (size_t)b * HWn * Cn;
    r.p0 = bh + (size_t)((y0 << 8) + xb) * Cn + csel * 8;
    r.p1 = bh + (size_t)((y1 << 8) + xb) * Cn + csel * 8;
    r.op = out + (size_t)b * Cn * HWn + (size_t)(csel * 8) * HWn + rem;
    return r;
}

// ---------------- Pass 2 (PDL secondary): 2 px/lane ----------------
__global__ void __launch_bounds__(256)
gauss_warp_main(const float* __restrict__ w,
                float* __restrict__ out)
{
    const int tid  = threadIdx.x;
    const int q    = tid >> 1;                    // pixel slot 0..127
    const int csel = tid & 1;                     // channel half

    const int pA = blockIdx.x * 256 + q;
    const int pB = pA + 128;

    // -------- prologue: depends only on w; overlaps the transpose --------
    const PixParams a  = pix_params(pA, csel, w, out);
    const PixParams bp = pix_params(pB, csel, w, out);

#if __CUDA_ARCH__ >= 900
    cudaGridDependencySynchronize();    // scratch now fully visible
#endif

    // -------- gathers: all 8 issued up front (MLP = 8/lane) --------
    const uint4 a00 = __ldg((const uint4*)a.p0);
    const uint4 a01 = __ldg((const uint4*)a.p0 + 2);
    const uint4 a10 = __ldg((const uint4*)a.p1);
    const uint4 a11 = __ldg((const uint4*)a.p1 + 2);
    const uint4 b00 = __ldg((const uint4*)bp.p0);
    const uint4 b01 = __ldg((const uint4*)bp.p0 + 2);
    const uint4 b10 = __ldg((const uint4*)bp.p1);
    const uint4 b11 = __ldg((const uint4*)bp.p1 + 2);

    unsigned long long s0, s1, s2, s3;
    s0 = mul2(a.W00, h2f2(a00.x));
    s1 = mul2(a.W00, h2f2(a00.y));
    s2 = mul2(a.W00, h2f2(a00.z));
    s3 = mul2(a.W00, h2f2(a00.w));
    s0 = fma2(a.W01, h2f2(a01.x), s0);
    s1 = fma2(a.W01, h2f2(a01.y), s1);
    s2 = fma2(a.W01, h2f2(a01.z), s2);
    s3 = fma2(a.W01, h2f2(a01.w), s3);
    s0 = fma2(a.W10, h2f2(a10.x), s0);
    s1 = fma2(a.W10, h2f2(a10.y), s1);
    s2 = fma2(a.W10, h2f2(a10.z), s2);
    s3 = fma2(a.W10, h2f2(a10.w), s3);
    s0 = fma2(a.W11, h2f2(a11.x), s0);
    s1 = fma2(a.W11, h2f2(a11.y), s1);
    s2 = fma2(a.W11, h2f2(a11.z), s2);
    s3 = fma2(a.W11, h2f2(a11.w), s3);
    {
        const float2 f0 = f2unpack(s0);
        const float2 f1 = f2unpack(s1);
        const float2 f2 = f2unpack(s2);
        const float2 f3 = f2unpack(s3);
        a.op[0 * HWn] = f0.x;  a.op[1 * HWn] = f0.y;
        a.op[2 * HWn] = f1.x;  a.op[3 * HWn] = f1.y;
        a.op[4 * HWn] = f2.x;  a.op[5 * HWn] = f2.y;
        a.op[6 * HWn] = f3.x;  a.op[7 * HWn] = f3.y;
    }

    s0 = mul2(bp.W00, h2f2(b00.x));
    s1 = mul2(bp.W00, h2f2(b00.y));
    s2 = mul2(bp.W00, h2f2(b00.z));
    s3 = mul2(bp.W00, h2f2(b00.w));
    s0 = fma2(bp.W01, h2f2(b01.x), s0);
    s1 = fma2(bp.W01, h2f2(b01.y), s1);
    s2 = fma2(bp.W01, h2f2(b01.z), s2);
    s3 = fma2(bp.W01, h2f2(b01.w), s3);
    s0 = fma2(bp.W10, h2f2(b10.x), s0);
    s1 = fma2(bp.W10, h2f2(b10.y), s1);
    s2 = fma2(bp.W10, h2f2(b10.z), s2);
    s3 = fma2(bp.W10, h2f2(b10.w), s3);
    s0 = fma2(bp.W11, h2f2(b11.x), s0);
    s1 = fma2(bp.W11, h2f2(b11.y), s1);
    s2 = fma2(bp.W11, h2f2(b11.z), s2);
    s3 = fma2(bp.W11, h2f2(b11.w), s3);
    {
        const float2 f0 = f2unpack(s0);
        const float2 f1 = f2unpack(s1);
        const float2 f2 = f2unpack(s2);
        const float2 f3 = f2unpack(s3);
        bp.op[0 * HWn] = f0.x;  bp.op[1 * HWn] = f0.y;
        bp.op[2 * HWn] = f1.x;  bp.op[3 * HWn] = f1.y;
        bp.op[4 * HWn] = f2.x;  bp.op[5 * HWn] = f2.y;
        bp.op[6 * HWn] = f3.x;  bp.op[7 * HWn] = f3.y;
    }
}

extern "C" void kernel_launch(void* const* d_in, const int* in_sizes, int n_in,
                              void* d_out, int out_size)
{
    const float* im = (const float*)d_in[0];
    const float* w  = (const float*)d_in[1];
    if (n_in >= 2 && in_sizes[0] == Bn * 2 * HWn && in_sizes[1] == Bn * Cn * HWn) {
        im = (const float*)d_in[1];
        w  = (const float*)d_in[0];
    }
    float* out = (float*)d_out;

    transpose_chw_hwc<<<Bn * Hn, 256>>>(im);

    // PDL: main launches while transpose drains; prologue overlaps it.
    cudaLaunchConfig_t cfg = {};
    cfg.gridDim  = dim3((Bn * HWn) / 256, 1, 1);
    cfg.blockDim = dim3(256, 1, 1);
    cudaLaunchAttribute attr[1];
    attr[0].id = cudaLaunchAttributeProgrammaticStreamSerialization;
    attr[0].val.programmaticStreamSerializationAllowed = 1;
    cfg.attrs = attr;
    cfg.numAttrs = 1;
    cudaLaunchKernelEx(&cfg, gauss_warp_main, w, out);
}